// round 8
// baseline (speedup 1.0000x reference)
#include <cuda_runtime.h>

// IMU preintegration (RmiModel). Associative segment composition:
//   segment = (Q, p, r, tau);
//   compose: Q=Q1Q2, p=p1+Q1 p2, r=r1+tau2 p1+Q1 r2, tau=tau1+tau2.
// 4 warps per batch (block = 128 thr = 1 batch). Each lane integrates 8
// contiguous steps as TWO chains of 4 steps PACKED into f32x2 (A=.lo, B=.hi),
// one scalar compose merges A∘B, then a 5-stage shfl_down tree composes the
// 32 lane segments (valid on lane 0). Warp totals composed via smem.

typedef unsigned long long u64;

__device__ __forceinline__ u64 pk2(float lo, float hi) {
    u64 r;
    asm("mov.b64 %0, {%1, %2};" : "=l"(r)
        : "r"(__float_as_uint(lo)), "r"(__float_as_uint(hi)));
    return r;
}
__device__ __forceinline__ void up2(u64 v, float& lo, float& hi) {
    unsigned int a, b;
    asm("mov.b64 {%0, %1}, %2;" : "=r"(a), "=r"(b) : "l"(v));
    lo = __uint_as_float(a); hi = __uint_as_float(b);
}
__device__ __forceinline__ u64 dup2(float c) { return pk2(c, c); }
__device__ __forceinline__ u64 f2fma(u64 a, u64 b, u64 c) {
    u64 d; asm("fma.rn.f32x2 %0, %1, %2, %3;" : "=l"(d) : "l"(a), "l"(b), "l"(c)); return d;
}
__device__ __forceinline__ u64 f2mul(u64 a, u64 b) {
    u64 d; asm("mul.rn.f32x2 %0, %1, %2;" : "=l"(d) : "l"(a), "l"(b)); return d;
}
__device__ __forceinline__ u64 f2add(u64 a, u64 b) {
    u64 d; asm("add.rn.f32x2 %0, %1, %2;" : "=l"(d) : "l"(a), "l"(b)); return d;
}
__device__ __forceinline__ u64 f2neg(u64 a) { return a ^ 0x8000000080000000ULL; }

// Packed so3 exponential: R = I + A*K + Bc*(phi phi^T - t2 I), both halves.
__device__ __forceinline__ void pso3_R(u64 px, u64 py, u64 pz, u64 R[9]) {
    u64 px2 = f2mul(px, px), py2 = f2mul(py, py), pz2 = f2mul(pz, pz);
    u64 syz = f2add(py2, pz2), sxz = f2add(px2, pz2), sxy = f2add(px2, py2);
    u64 t2  = f2add(px2, syz);
    const u64 ONE = dup2(1.0f);
    u64 A  = f2fma(t2, dup2(1.0f/120.0f), dup2(-1.0f/6.0f));
    A      = f2fma(t2, A, ONE);
    u64 Bc = f2fma(t2, dup2(1.0f/720.0f), dup2(-1.0f/24.0f));
    Bc     = f2fma(t2, Bc, dup2(0.5f));

    // Cold exact fallback for large angles (never taken on this data).
    float t2lo, t2hi; up2(t2, t2lo, t2hi);
    if (__builtin_expect(fmaxf(t2lo, t2hi) > 0.25f, 0)) {
        float Alo, Ahi, Blo, Bhi;
        up2(A, Alo, Ahi); up2(Bc, Blo, Bhi);
        if (t2lo > 0.25f) {
            float th = __fsqrt_rn(t2lo); float s, c; __sincosf(th, &s, &c);
            Alo = s / th; Blo = (1.0f - c) / t2lo;
        }
        if (t2hi > 0.25f) {
            float th = __fsqrt_rn(t2hi); float s, c; __sincosf(th, &s, &c);
            Ahi = s / th; Bhi = (1.0f - c) / t2hi;
        }
        A = pk2(Alo, Ahi); Bc = pk2(Blo, Bhi);
    }

    u64 nBc = f2neg(Bc);
    u64 An  = f2neg(A);
    R[0] = f2fma(nBc, syz, ONE);
    R[4] = f2fma(nBc, sxz, ONE);
    R[8] = f2fma(nBc, sxy, ONE);
    u64 Bxy = f2mul(Bc, f2mul(px, py));
    u64 Bxz = f2mul(Bc, f2mul(px, pz));
    u64 Byz = f2mul(Bc, f2mul(py, pz));
    R[3] = f2fma(A,  pz, Bxy);
    R[1] = f2fma(An, pz, Bxy);
    R[2] = f2fma(A,  py, Bxz);
    R[6] = f2fma(An, py, Bxz);
    R[7] = f2fma(A,  px, Byz);
    R[5] = f2fma(An, px, Byz);
}

// First step from identity (packed both chains).
__device__ __forceinline__ void pstep0(u64 Q[9], u64 p[3], u64 r[3], u64& tau,
                                       u64 dt, u64 aX, u64 aY, u64 aZ,
                                       u64 wX, u64 wY, u64 wZ) {
    u64 hdt2 = f2mul(dup2(0.5f), f2mul(dt, dt));
    r[0] = f2mul(aX, hdt2); r[1] = f2mul(aY, hdt2); r[2] = f2mul(aZ, hdt2);
    p[0] = f2mul(aX, dt);   p[1] = f2mul(aY, dt);   p[2] = f2mul(aZ, dt);
    tau  = dt;
    pso3_R(f2mul(wX, dt), f2mul(wY, dt), f2mul(wZ, dt), Q);
}

// General packed step.
__device__ __forceinline__ void pstep(u64 Q[9], u64 p[3], u64 r[3], u64& tau,
                                      u64 dt, u64 aX, u64 aY, u64 aZ,
                                      u64 wX, u64 wY, u64 wZ) {
    u64 ca0 = f2fma(Q[0], aX, f2fma(Q[1], aY, f2mul(Q[2], aZ)));
    u64 ca1 = f2fma(Q[3], aX, f2fma(Q[4], aY, f2mul(Q[5], aZ)));
    u64 ca2 = f2fma(Q[6], aX, f2fma(Q[7], aY, f2mul(Q[8], aZ)));
    u64 hdt2 = f2mul(dup2(0.5f), f2mul(dt, dt));
    r[0] = f2fma(p[0], dt, f2fma(ca0, hdt2, r[0]));
    r[1] = f2fma(p[1], dt, f2fma(ca1, hdt2, r[1]));
    r[2] = f2fma(p[2], dt, f2fma(ca2, hdt2, r[2]));
    p[0] = f2fma(ca0, dt, p[0]);
    p[1] = f2fma(ca1, dt, p[1]);
    p[2] = f2fma(ca2, dt, p[2]);
    tau  = f2add(tau, dt);

    u64 R[9];
    pso3_R(f2mul(wX, dt), f2mul(wY, dt), f2mul(wZ, dt), R);

    u64 n0 = f2fma(Q[0], R[0], f2fma(Q[1], R[3], f2mul(Q[2], R[6])));
    u64 n1 = f2fma(Q[0], R[1], f2fma(Q[1], R[4], f2mul(Q[2], R[7])));
    u64 n2 = f2fma(Q[0], R[2], f2fma(Q[1], R[5], f2mul(Q[2], R[8])));
    u64 n3 = f2fma(Q[3], R[0], f2fma(Q[4], R[3], f2mul(Q[5], R[6])));
    u64 n4 = f2fma(Q[3], R[1], f2fma(Q[4], R[4], f2mul(Q[5], R[7])));
    u64 n5 = f2fma(Q[3], R[2], f2fma(Q[4], R[5], f2mul(Q[5], R[8])));
    u64 n6 = f2fma(Q[6], R[0], f2fma(Q[7], R[3], f2mul(Q[8], R[6])));
    u64 n7 = f2fma(Q[6], R[1], f2fma(Q[7], R[4], f2mul(Q[8], R[7])));
    u64 n8 = f2fma(Q[6], R[2], f2fma(Q[7], R[5], f2mul(Q[8], R[8])));
    Q[0]=n0; Q[1]=n1; Q[2]=n2;
    Q[3]=n3; Q[4]=n4; Q[5]=n5;
    Q[6]=n6; Q[7]=n7; Q[8]=n8;
}

// Scalar compose: T1 <- T1 ∘ T2
__device__ __forceinline__ void compose(float Q1[9], float p1[3], float r1[3], float& tau1,
                                        const float Q2[9], const float p2[3],
                                        const float r2[3], float tau2) {
    float nQ[9];
    #pragma unroll
    for (int i = 0; i < 3; i++) {
        #pragma unroll
        for (int j = 0; j < 3; j++)
            nQ[3*i+j] = Q1[3*i+0]*Q2[0+j] + Q1[3*i+1]*Q2[3+j] + Q1[3*i+2]*Q2[6+j];
    }
    float np[3], nr[3];
    #pragma unroll
    for (int i = 0; i < 3; i++) {
        float Qp = Q1[3*i+0]*p2[0] + Q1[3*i+1]*p2[1] + Q1[3*i+2]*p2[2];
        float Qr = Q1[3*i+0]*r2[0] + Q1[3*i+1]*r2[1] + Q1[3*i+2]*r2[2];
        np[i] = p1[i] + Qp;
        nr[i] = r1[i] + tau2 * p1[i] + Qr;
    }
    #pragma unroll
    for (int i = 0; i < 9; i++) Q1[i] = nQ[i];
    #pragma unroll
    for (int i = 0; i < 3; i++) { p1[i] = np[i]; r1[i] = nr[i]; }
    tau1 += tau2;
}

// Load 6 channels (w,a) as float4 at offset kk, tail-guarded.
__device__ __forceinline__ void load6(const float* __restrict__ w0, const float* __restrict__ w1,
                                      const float* __restrict__ w2, const float* __restrict__ a0,
                                      const float* __restrict__ a1, const float* __restrict__ a2,
                                      int kk, int T,
                                      float4& vwx, float4& vwy, float4& vwz,
                                      float4& vax, float4& vay, float4& vaz) {
    if (kk + 3 < T) {
        vwx = *reinterpret_cast<const float4*>(w0 + kk);
        vwy = *reinterpret_cast<const float4*>(w1 + kk);
        vwz = *reinterpret_cast<const float4*>(w2 + kk);
        vax = *reinterpret_cast<const float4*>(a0 + kk);
        vay = *reinterpret_cast<const float4*>(a1 + kk);
        vaz = *reinterpret_cast<const float4*>(a2 + kk);
    } else {
        float tmp[6][4];
        #pragma unroll
        for (int j = 0; j < 4; j++) {
            bool ok = (kk + j) < T;
            tmp[0][j] = ok ? w0[kk + j] : 0.f;
            tmp[1][j] = ok ? w1[kk + j] : 0.f;
            tmp[2][j] = ok ? w2[kk + j] : 0.f;
            tmp[3][j] = ok ? a0[kk + j] : 0.f;
            tmp[4][j] = ok ? a1[kk + j] : 0.f;
            tmp[5][j] = ok ? a2[kk + j] : 0.f;
        }
        vwx = make_float4(tmp[0][0], tmp[0][1], tmp[0][2], tmp[0][3]);
        vwy = make_float4(tmp[1][0], tmp[1][1], tmp[1][2], tmp[1][3]);
        vwz = make_float4(tmp[2][0], tmp[2][1], tmp[2][2], tmp[2][3]);
        vax = make_float4(tmp[3][0], tmp[3][1], tmp[3][2], tmp[3][3]);
        vay = make_float4(tmp[4][0], tmp[4][1], tmp[4][2], tmp[4][3]);
        vaz = make_float4(tmp[5][0], tmp[5][1], tmp[5][2], tmp[5][3]);
    }
}

// One 256-step round for this warp. Result (valid on lane 0) in (Q,p,r,tau).
__device__ __forceinline__ void warp_round(const float* __restrict__ tt,
                                           const float* __restrict__ w0,
                                           const float* __restrict__ w1,
                                           const float* __restrict__ w2,
                                           const float* __restrict__ a0,
                                           const float* __restrict__ a1,
                                           const float* __restrict__ a2,
                                           int k, int T, int nsteps, int lane,
                                           float Q[9], float p[3], float r[3], float& tau) {
    // ---- time channel -> packed DT[4] (tv/dts die before the w/a loads) ----
    u64 DT[4];
    {
        float tv[8];
        if (k + 7 < T) {
            float4 u = *reinterpret_cast<const float4*>(tt + k);
            float4 v = *reinterpret_cast<const float4*>(tt + k + 4);
            tv[0]=u.x; tv[1]=u.y; tv[2]=u.z; tv[3]=u.w;
            tv[4]=v.x; tv[5]=v.y; tv[6]=v.z; tv[7]=v.w;
        } else {
            #pragma unroll
            for (int j = 0; j < 8; j++) tv[j] = (k + j < T) ? tt[k + j] : 0.f;
        }
        float tnext = __shfl_down_sync(0xffffffffu, tv[0], 1);
        if (lane == 31) {
            int kn = k + 8;
            tnext = (kn < T) ? tt[kn] : 0.f;
        }
        float dts[8];
        #pragma unroll
        for (int j = 0; j < 7; j++) dts[j] = tv[j + 1] - tv[j];
        dts[7] = tnext - tv[7];
        #pragma unroll
        for (int j = 0; j < 8; j++)
            if (k + j >= nsteps) dts[j] = 0.f;     // identity step
        #pragma unroll
        for (int j = 0; j < 4; j++) DT[j] = pk2(dts[j], dts[j + 4]);
    }

    // ---- load both 4-step chains, pack chainA=.lo / chainB=.hi ----
    float4 wxA, wyA, wzA, axA, ayA, azA;
    float4 wxB, wyB, wzB, axB, ayB, azB;
    load6(w0, w1, w2, a0, a1, a2, k,     T, wxA, wyA, wzA, axA, ayA, azA);
    load6(w0, w1, w2, a0, a1, a2, k + 4, T, wxB, wyB, wzB, axB, ayB, azB);

    // ---- integrate both chains simultaneously (packed) ----
    u64 PQ[9], PP[3], PR[3], PT;
    pstep0(PQ, PP, PR, PT, DT[0],
           pk2(axA.x, axB.x), pk2(ayA.x, ayB.x), pk2(azA.x, azB.x),
           pk2(wxA.x, wxB.x), pk2(wyA.x, wyB.x), pk2(wzA.x, wzB.x));
    pstep (PQ, PP, PR, PT, DT[1],
           pk2(axA.y, axB.y), pk2(ayA.y, ayB.y), pk2(azA.y, azB.y),
           pk2(wxA.y, wxB.y), pk2(wyA.y, wyB.y), pk2(wzA.y, wzB.y));
    pstep (PQ, PP, PR, PT, DT[2],
           pk2(axA.z, axB.z), pk2(ayA.z, ayB.z), pk2(azA.z, azB.z),
           pk2(wxA.z, wxB.z), pk2(wyA.z, wyB.z), pk2(wzA.z, wzB.z));
    pstep (PQ, PP, PR, PT, DT[3],
           pk2(axA.w, axB.w), pk2(ayA.w, ayB.w), pk2(azA.w, azB.w),
           pk2(wxA.w, wxB.w), pk2(wyA.w, wyB.w), pk2(wzA.w, wzB.w));

    // ---- unpack, compose chainA ∘ chainB ----
    float QB[9], pB[3], rB[3], tauB;
    #pragma unroll
    for (int i = 0; i < 9; i++) up2(PQ[i], Q[i], QB[i]);
    #pragma unroll
    for (int i = 0; i < 3; i++) { up2(PP[i], p[i], pB[i]); up2(PR[i], r[i], rB[i]); }
    up2(PT, tau, tauB);
    compose(Q, p, r, tau, QB, pB, rB, tauB);

    // ---- warp tree reduce (ordered, valid on lane 0) ----
    #pragma unroll
    for (int off = 1; off < 32; off <<= 1) {
        float Q2[9], p2[3], r2[3], tau2;
        #pragma unroll
        for (int i = 0; i < 9; i++) Q2[i] = __shfl_down_sync(0xffffffffu, Q[i], off);
        #pragma unroll
        for (int i = 0; i < 3; i++) p2[i] = __shfl_down_sync(0xffffffffu, p[i], off);
        #pragma unroll
        for (int i = 0; i < 3; i++) r2[i] = __shfl_down_sync(0xffffffffu, r[i], off);
        tau2 = __shfl_down_sync(0xffffffffu, tau, off);
        compose(Q, p, r, tau, Q2, p2, r2, tau2);
    }
}

__global__ __launch_bounds__(128, 6)
void rmi_kernel(const float* __restrict__ x, float* __restrict__ out,
                int T, int chunk)
{
    const int b    = blockIdx.x;
    const int warp = threadIdx.x >> 5;
    const int lane = threadIdx.x & 31;
    const int nsteps = T - 1;

    const size_t base = (size_t)b * 7 * (size_t)T;
    const float* tt = x + base;
    const float* w0 = tt + T;
    const float* w1 = w0 + T;
    const float* w2 = w1 + T;
    const float* a0 = w2 + T;
    const float* a1 = a0 + T;
    const float* a2 = a1 + T;

    const int rounds = chunk >> 8;   // 256 steps per round

    // Round 0 -> warp total directly (total not live during integration)
    float TQ[9], Tp[3], Tr[3], Ttau;
    warp_round(tt, w0, w1, w2, a0, a1, a2,
               warp * chunk + lane * 8, T, nsteps, lane, TQ, Tp, Tr, Ttau);

    for (int rr = 1; rr < rounds; rr++) {
        float Q[9], p[3], r[3], tau;
        warp_round(tt, w0, w1, w2, a0, a1, a2,
                   warp * chunk + rr * 256 + lane * 8, T, nsteps, lane, Q, p, r, tau);
        compose(TQ, Tp, Tr, Ttau, Q, p, r, tau);
    }

    // ---- cross-warp combine via smem ----
    __shared__ float seg[4][16];
    if (lane == 0) {
        #pragma unroll
        for (int i = 0; i < 9; i++) seg[warp][i] = TQ[i];
        seg[warp][9]  = Tp[0]; seg[warp][10] = Tp[1]; seg[warp][11] = Tp[2];
        seg[warp][12] = Tr[0]; seg[warp][13] = Tr[1]; seg[warp][14] = Tr[2];
        seg[warp][15] = Ttau;
    }
    __syncthreads();

    if (warp == 0 && lane == 0) {
        float FQ[9], Fp[3], Fr[3], Ftau;
        #pragma unroll
        for (int i = 0; i < 9; i++) FQ[i] = seg[0][i];
        Fp[0]=seg[0][9];  Fp[1]=seg[0][10]; Fp[2]=seg[0][11];
        Fr[0]=seg[0][12]; Fr[1]=seg[0][13]; Fr[2]=seg[0][14];
        Ftau = seg[0][15];
        #pragma unroll
        for (int wsg = 1; wsg < 4; wsg++) {
            float Q2[9], p2[3], r2[3], tau2;
            #pragma unroll
            for (int i = 0; i < 9; i++) Q2[i] = seg[wsg][i];
            p2[0]=seg[wsg][9];  p2[1]=seg[wsg][10]; p2[2]=seg[wsg][11];
            r2[0]=seg[wsg][12]; r2[1]=seg[wsg][13]; r2[2]=seg[wsg][14];
            tau2 = seg[wsg][15];
            compose(FQ, Fp, Fr, Ftau, Q2, p2, r2, tau2);
        }
        float* o = out + (size_t)b * 15;
        #pragma unroll
        for (int i = 0; i < 9; i++) o[i] = FQ[i];
        o[9]  = Fp[0]; o[10] = Fp[1]; o[11] = Fp[2];
        o[12] = Fr[0]; o[13] = Fr[1]; o[14] = Fr[2];
    }
}

extern "C" void kernel_launch(void* const* d_in, const int* in_sizes, int n_in,
                              void* d_out, int out_size) {
    const float* x = (const float*)d_in[0];
    float* out = (float*)d_out;

    int B = out_size / 15;
    int T = in_sizes[0] / (7 * B);
    int nsteps = T - 1;

    // per-warp contiguous chunk, multiple of 256, 4 warps cover all steps
    int chunk = ((nsteps + 1023) / 1024) * 256;

    rmi_kernel<<<B, 128>>>(x, out, T, chunk);
}

// round 9
// speedup vs baseline: 1.2884x; 1.2884x over previous
#include <cuda_runtime.h>

// IMU preintegration (RmiModel). Associative segment composition:
//   segment = (Q, p, r, tau);
//   compose: Q=Q1Q2, p=p1+Q1 p2, r=r1+tau2 p1+Q1 r2, tau=tau1+tau2.
// 4 warps per batch (block = 128 thr = 1 batch). Each lane integrates 8
// contiguous steps as TWO chains of 4 steps PACKED into f32x2 (A=.lo, B=.hi),
// one scalar compose merges A∘B, then a 5-stage shfl_down tree composes the
// 32 lane segments (valid on lane 0). Warp totals composed via smem.
// launch_bounds (128,5): ptxas's natural demand is ~96 regs; capping lower
// spills (measured R8 regression), so we keep 5 blocks/SM.

typedef unsigned long long u64;

__device__ __forceinline__ u64 pk2(float lo, float hi) {
    u64 r;
    asm("mov.b64 %0, {%1, %2};" : "=l"(r)
        : "r"(__float_as_uint(lo)), "r"(__float_as_uint(hi)));
    return r;
}
__device__ __forceinline__ void up2(u64 v, float& lo, float& hi) {
    unsigned int a, b;
    asm("mov.b64 {%0, %1}, %2;" : "=r"(a), "=r"(b) : "l"(v));
    lo = __uint_as_float(a); hi = __uint_as_float(b);
}
__device__ __forceinline__ u64 dup2(float c) { return pk2(c, c); }
__device__ __forceinline__ u64 f2fma(u64 a, u64 b, u64 c) {
    u64 d; asm("fma.rn.f32x2 %0, %1, %2, %3;" : "=l"(d) : "l"(a), "l"(b), "l"(c)); return d;
}
__device__ __forceinline__ u64 f2mul(u64 a, u64 b) {
    u64 d; asm("mul.rn.f32x2 %0, %1, %2;" : "=l"(d) : "l"(a), "l"(b)); return d;
}
__device__ __forceinline__ u64 f2add(u64 a, u64 b) {
    u64 d; asm("add.rn.f32x2 %0, %1, %2;" : "=l"(d) : "l"(a), "l"(b)); return d;
}
__device__ __forceinline__ u64 f2neg(u64 a) { return a ^ 0x8000000080000000ULL; }

// Packed so3 exponential: R = I + A*K + Bc*(phi phi^T - t2 I), both halves.
__device__ __forceinline__ void pso3_R(u64 px, u64 py, u64 pz, u64 R[9]) {
    u64 px2 = f2mul(px, px), py2 = f2mul(py, py), pz2 = f2mul(pz, pz);
    u64 syz = f2add(py2, pz2), sxz = f2add(px2, pz2), sxy = f2add(px2, py2);
    u64 t2  = f2add(px2, syz);
    const u64 ONE = dup2(1.0f);
    u64 A  = f2fma(t2, dup2(1.0f/120.0f), dup2(-1.0f/6.0f));
    A      = f2fma(t2, A, ONE);
    u64 Bc = f2fma(t2, dup2(1.0f/720.0f), dup2(-1.0f/24.0f));
    Bc     = f2fma(t2, Bc, dup2(0.5f));

    // Cold exact fallback for large angles (never taken on this data).
    float t2lo, t2hi; up2(t2, t2lo, t2hi);
    if (__builtin_expect(fmaxf(t2lo, t2hi) > 0.25f, 0)) {
        float Alo, Ahi, Blo, Bhi;
        up2(A, Alo, Ahi); up2(Bc, Blo, Bhi);
        if (t2lo > 0.25f) {
            float th = __fsqrt_rn(t2lo); float s, c; __sincosf(th, &s, &c);
            Alo = s / th; Blo = (1.0f - c) / t2lo;
        }
        if (t2hi > 0.25f) {
            float th = __fsqrt_rn(t2hi); float s, c; __sincosf(th, &s, &c);
            Ahi = s / th; Bhi = (1.0f - c) / t2hi;
        }
        A = pk2(Alo, Ahi); Bc = pk2(Blo, Bhi);
    }

    u64 nBc = f2neg(Bc);
    u64 An  = f2neg(A);
    R[0] = f2fma(nBc, syz, ONE);
    R[4] = f2fma(nBc, sxz, ONE);
    R[8] = f2fma(nBc, sxy, ONE);
    u64 Bxy = f2mul(Bc, f2mul(px, py));
    u64 Bxz = f2mul(Bc, f2mul(px, pz));
    u64 Byz = f2mul(Bc, f2mul(py, pz));
    R[3] = f2fma(A,  pz, Bxy);   // Bxy + A pz
    R[1] = f2fma(An, pz, Bxy);   // Bxy - A pz
    R[2] = f2fma(A,  py, Bxz);   // Bxz + A py
    R[6] = f2fma(An, py, Bxz);   // Bxz - A py
    R[7] = f2fma(A,  px, Byz);   // Byz + A px
    R[5] = f2fma(An, px, Byz);   // Byz - A px
}

// First step from identity (packed both chains).
__device__ __forceinline__ void pstep0(u64 Q[9], u64 p[3], u64 r[3], u64& tau,
                                       u64 dt, u64 aX, u64 aY, u64 aZ,
                                       u64 wX, u64 wY, u64 wZ) {
    u64 hdt2 = f2mul(dup2(0.5f), f2mul(dt, dt));
    r[0] = f2mul(aX, hdt2); r[1] = f2mul(aY, hdt2); r[2] = f2mul(aZ, hdt2);
    p[0] = f2mul(aX, dt);   p[1] = f2mul(aY, dt);   p[2] = f2mul(aZ, dt);
    tau  = dt;
    pso3_R(f2mul(wX, dt), f2mul(wY, dt), f2mul(wZ, dt), Q);
}

// General packed step.
__device__ __forceinline__ void pstep(u64 Q[9], u64 p[3], u64 r[3], u64& tau,
                                      u64 dt, u64 aX, u64 aY, u64 aZ,
                                      u64 wX, u64 wY, u64 wZ) {
    u64 ca0 = f2fma(Q[0], aX, f2fma(Q[1], aY, f2mul(Q[2], aZ)));
    u64 ca1 = f2fma(Q[3], aX, f2fma(Q[4], aY, f2mul(Q[5], aZ)));
    u64 ca2 = f2fma(Q[6], aX, f2fma(Q[7], aY, f2mul(Q[8], aZ)));
    u64 hdt2 = f2mul(dup2(0.5f), f2mul(dt, dt));
    r[0] = f2fma(p[0], dt, f2fma(ca0, hdt2, r[0]));
    r[1] = f2fma(p[1], dt, f2fma(ca1, hdt2, r[1]));
    r[2] = f2fma(p[2], dt, f2fma(ca2, hdt2, r[2]));
    p[0] = f2fma(ca0, dt, p[0]);
    p[1] = f2fma(ca1, dt, p[1]);
    p[2] = f2fma(ca2, dt, p[2]);
    tau  = f2add(tau, dt);

    u64 R[9];
    pso3_R(f2mul(wX, dt), f2mul(wY, dt), f2mul(wZ, dt), R);

    u64 n0 = f2fma(Q[0], R[0], f2fma(Q[1], R[3], f2mul(Q[2], R[6])));
    u64 n1 = f2fma(Q[0], R[1], f2fma(Q[1], R[4], f2mul(Q[2], R[7])));
    u64 n2 = f2fma(Q[0], R[2], f2fma(Q[1], R[5], f2mul(Q[2], R[8])));
    u64 n3 = f2fma(Q[3], R[0], f2fma(Q[4], R[3], f2mul(Q[5], R[6])));
    u64 n4 = f2fma(Q[3], R[1], f2fma(Q[4], R[4], f2mul(Q[5], R[7])));
    u64 n5 = f2fma(Q[3], R[2], f2fma(Q[4], R[5], f2mul(Q[5], R[8])));
    u64 n6 = f2fma(Q[6], R[0], f2fma(Q[7], R[3], f2mul(Q[8], R[6])));
    u64 n7 = f2fma(Q[6], R[1], f2fma(Q[7], R[4], f2mul(Q[8], R[7])));
    u64 n8 = f2fma(Q[6], R[2], f2fma(Q[7], R[5], f2mul(Q[8], R[8])));
    Q[0]=n0; Q[1]=n1; Q[2]=n2;
    Q[3]=n3; Q[4]=n4; Q[5]=n5;
    Q[6]=n6; Q[7]=n7; Q[8]=n8;
}

// Scalar compose: T1 <- T1 ∘ T2
__device__ __forceinline__ void compose(float Q1[9], float p1[3], float r1[3], float& tau1,
                                        const float Q2[9], const float p2[3],
                                        const float r2[3], float tau2) {
    float nQ[9];
    #pragma unroll
    for (int i = 0; i < 3; i++) {
        #pragma unroll
        for (int j = 0; j < 3; j++)
            nQ[3*i+j] = Q1[3*i+0]*Q2[0+j] + Q1[3*i+1]*Q2[3+j] + Q1[3*i+2]*Q2[6+j];
    }
    float np[3], nr[3];
    #pragma unroll
    for (int i = 0; i < 3; i++) {
        float Qp = Q1[3*i+0]*p2[0] + Q1[3*i+1]*p2[1] + Q1[3*i+2]*p2[2];
        float Qr = Q1[3*i+0]*r2[0] + Q1[3*i+1]*r2[1] + Q1[3*i+2]*r2[2];
        np[i] = p1[i] + Qp;
        nr[i] = r1[i] + tau2 * p1[i] + Qr;
    }
    #pragma unroll
    for (int i = 0; i < 9; i++) Q1[i] = nQ[i];
    #pragma unroll
    for (int i = 0; i < 3; i++) { p1[i] = np[i]; r1[i] = nr[i]; }
    tau1 += tau2;
}

// Load 6 channels (w,a) as float4 at offset kk, tail-guarded.
__device__ __forceinline__ void load6(const float* __restrict__ w0, const float* __restrict__ w1,
                                      const float* __restrict__ w2, const float* __restrict__ a0,
                                      const float* __restrict__ a1, const float* __restrict__ a2,
                                      int kk, int T,
                                      float4& vwx, float4& vwy, float4& vwz,
                                      float4& vax, float4& vay, float4& vaz) {
    if (kk + 3 < T) {
        vwx = *reinterpret_cast<const float4*>(w0 + kk);
        vwy = *reinterpret_cast<const float4*>(w1 + kk);
        vwz = *reinterpret_cast<const float4*>(w2 + kk);
        vax = *reinterpret_cast<const float4*>(a0 + kk);
        vay = *reinterpret_cast<const float4*>(a1 + kk);
        vaz = *reinterpret_cast<const float4*>(a2 + kk);
    } else {
        float tmp[6][4];
        #pragma unroll
        for (int j = 0; j < 4; j++) {
            bool ok = (kk + j) < T;
            tmp[0][j] = ok ? w0[kk + j] : 0.f;
            tmp[1][j] = ok ? w1[kk + j] : 0.f;
            tmp[2][j] = ok ? w2[kk + j] : 0.f;
            tmp[3][j] = ok ? a0[kk + j] : 0.f;
            tmp[4][j] = ok ? a1[kk + j] : 0.f;
            tmp[5][j] = ok ? a2[kk + j] : 0.f;
        }
        vwx = make_float4(tmp[0][0], tmp[0][1], tmp[0][2], tmp[0][3]);
        vwy = make_float4(tmp[1][0], tmp[1][1], tmp[1][2], tmp[1][3]);
        vwz = make_float4(tmp[2][0], tmp[2][1], tmp[2][2], tmp[2][3]);
        vax = make_float4(tmp[3][0], tmp[3][1], tmp[3][2], tmp[3][3]);
        vay = make_float4(tmp[4][0], tmp[4][1], tmp[4][2], tmp[4][3]);
        vaz = make_float4(tmp[5][0], tmp[5][1], tmp[5][2], tmp[5][3]);
    }
}

// One 256-step round for this warp. Result (valid on lane 0) in (Q,p,r,tau).
__device__ __forceinline__ void warp_round(const float* __restrict__ tt,
                                           const float* __restrict__ w0,
                                           const float* __restrict__ w1,
                                           const float* __restrict__ w2,
                                           const float* __restrict__ a0,
                                           const float* __restrict__ a1,
                                           const float* __restrict__ a2,
                                           int k, int T, int nsteps, int lane,
                                           float Q[9], float p[3], float r[3], float& tau) {
    // ---- time channel & dts ----
    float tv[8];
    if (k + 7 < T) {
        float4 u = *reinterpret_cast<const float4*>(tt + k);
        float4 v = *reinterpret_cast<const float4*>(tt + k + 4);
        tv[0]=u.x; tv[1]=u.y; tv[2]=u.z; tv[3]=u.w;
        tv[4]=v.x; tv[5]=v.y; tv[6]=v.z; tv[7]=v.w;
    } else {
        #pragma unroll
        for (int j = 0; j < 8; j++) tv[j] = (k + j < T) ? tt[k + j] : 0.f;
    }
    float tnext = __shfl_down_sync(0xffffffffu, tv[0], 1);
    if (lane == 31) {
        int kn = k + 8;
        tnext = (kn < T) ? tt[kn] : 0.f;
    }
    float dts[8];
    #pragma unroll
    for (int j = 0; j < 7; j++) dts[j] = tv[j + 1] - tv[j];
    dts[7] = tnext - tv[7];
    #pragma unroll
    for (int j = 0; j < 8; j++)
        if (k + j >= nsteps) dts[j] = 0.f;     // identity step

    // ---- load both 4-step chains, pack chainA=.lo / chainB=.hi ----
    float4 wxA, wyA, wzA, axA, ayA, azA;
    float4 wxB, wyB, wzB, axB, ayB, azB;
    load6(w0, w1, w2, a0, a1, a2, k,     T, wxA, wyA, wzA, axA, ayA, azA);
    load6(w0, w1, w2, a0, a1, a2, k + 4, T, wxB, wyB, wzB, axB, ayB, azB);

    u64 DT[4]  = { pk2(dts[0], dts[4]), pk2(dts[1], dts[5]),
                   pk2(dts[2], dts[6]), pk2(dts[3], dts[7]) };

    // ---- integrate both chains simultaneously (packed) ----
    u64 PQ[9], PP[3], PR[3], PT;
    pstep0(PQ, PP, PR, PT, DT[0],
           pk2(axA.x, axB.x), pk2(ayA.x, ayB.x), pk2(azA.x, azB.x),
           pk2(wxA.x, wxB.x), pk2(wyA.x, wyB.x), pk2(wzA.x, wzB.x));
    pstep (PQ, PP, PR, PT, DT[1],
           pk2(axA.y, axB.y), pk2(ayA.y, ayB.y), pk2(azA.y, azB.y),
           pk2(wxA.y, wxB.y), pk2(wyA.y, wyB.y), pk2(wzA.y, wzB.y));
    pstep (PQ, PP, PR, PT, DT[2],
           pk2(axA.z, axB.z), pk2(ayA.z, ayB.z), pk2(azA.z, azB.z),
           pk2(wxA.z, wxB.z), pk2(wyA.z, wyB.z), pk2(wzA.z, wzB.z));
    pstep (PQ, PP, PR, PT, DT[3],
           pk2(axA.w, axB.w), pk2(ayA.w, ayB.w), pk2(azA.w, azB.w),
           pk2(wxA.w, wxB.w), pk2(wyA.w, wyB.w), pk2(wzA.w, wzB.w));

    // ---- unpack, compose chainA ∘ chainB ----
    float QB[9], pB[3], rB[3], tauB;
    #pragma unroll
    for (int i = 0; i < 9; i++) up2(PQ[i], Q[i], QB[i]);
    #pragma unroll
    for (int i = 0; i < 3; i++) { up2(PP[i], p[i], pB[i]); up2(PR[i], r[i], rB[i]); }
    up2(PT, tau, tauB);
    compose(Q, p, r, tau, QB, pB, rB, tauB);

    // ---- warp tree reduce (ordered, valid on lane 0) ----
    #pragma unroll
    for (int off = 1; off < 32; off <<= 1) {
        float Q2[9], p2[3], r2[3], tau2;
        #pragma unroll
        for (int i = 0; i < 9; i++) Q2[i] = __shfl_down_sync(0xffffffffu, Q[i], off);
        #pragma unroll
        for (int i = 0; i < 3; i++) p2[i] = __shfl_down_sync(0xffffffffu, p[i], off);
        #pragma unroll
        for (int i = 0; i < 3; i++) r2[i] = __shfl_down_sync(0xffffffffu, r[i], off);
        tau2 = __shfl_down_sync(0xffffffffu, tau, off);
        compose(Q, p, r, tau, Q2, p2, r2, tau2);
    }
}

__global__ __launch_bounds__(128, 5)
void rmi_kernel(const float* __restrict__ x, float* __restrict__ out,
                int T, int chunk)
{
    const int b    = blockIdx.x;
    const int warp = threadIdx.x >> 5;
    const int lane = threadIdx.x & 31;
    const int nsteps = T - 1;

    const size_t base = (size_t)b * 7 * (size_t)T;
    const float* tt = x + base;
    const float* w0 = tt + T;
    const float* w1 = w0 + T;
    const float* w2 = w1 + T;
    const float* a0 = w2 + T;
    const float* a1 = a0 + T;
    const float* a2 = a1 + T;

    const int rounds = chunk >> 8;   // 256 steps per round

    // Round 0 -> warp total directly (total not live during integration)
    float TQ[9], Tp[3], Tr[3], Ttau;
    warp_round(tt, w0, w1, w2, a0, a1, a2,
               warp * chunk + lane * 8, T, nsteps, lane, TQ, Tp, Tr, Ttau);

    for (int rr = 1; rr < rounds; rr++) {
        float Q[9], p[3], r[3], tau;
        warp_round(tt, w0, w1, w2, a0, a1, a2,
                   warp * chunk + rr * 256 + lane * 8, T, nsteps, lane, Q, p, r, tau);
        compose(TQ, Tp, Tr, Ttau, Q, p, r, tau);
    }

    // ---- cross-warp combine via smem ----
    __shared__ float seg[4][16];
    if (lane == 0) {
        #pragma unroll
        for (int i = 0; i < 9; i++) seg[warp][i] = TQ[i];
        seg[warp][9]  = Tp[0]; seg[warp][10] = Tp[1]; seg[warp][11] = Tp[2];
        seg[warp][12] = Tr[0]; seg[warp][13] = Tr[1]; seg[warp][14] = Tr[2];
        seg[warp][15] = Ttau;
    }
    __syncthreads();

    if (warp == 0 && lane == 0) {
        float FQ[9], Fp[3], Fr[3], Ftau;
        #pragma unroll
        for (int i = 0; i < 9; i++) FQ[i] = seg[0][i];
        Fp[0]=seg[0][9];  Fp[1]=seg[0][10]; Fp[2]=seg[0][11];
        Fr[0]=seg[0][12]; Fr[1]=seg[0][13]; Fr[2]=seg[0][14];
        Ftau = seg[0][15];
        #pragma unroll
        for (int wsg = 1; wsg < 4; wsg++) {
            float Q2[9], p2[3], r2[3], tau2;
            #pragma unroll
            for (int i = 0; i < 9; i++) Q2[i] = seg[wsg][i];
            p2[0]=seg[wsg][9];  p2[1]=seg[wsg][10]; p2[2]=seg[wsg][11];
            r2[0]=seg[wsg][12]; r2[1]=seg[wsg][13]; r2[2]=seg[wsg][14];
            tau2 = seg[wsg][15];
            compose(FQ, Fp, Fr, Ftau, Q2, p2, r2, tau2);
        }
        float* o = out + (size_t)b * 15;
        #pragma unroll
        for (int i = 0; i < 9; i++) o[i] = FQ[i];
        o[9]  = Fp[0]; o[10] = Fp[1]; o[11] = Fp[2];
        o[12] = Fr[0]; o[13] = Fr[1]; o[14] = Fr[2];
    }
}

extern "C" void kernel_launch(void* const* d_in, const int* in_sizes, int n_in,
                              void* d_out, int out_size) {
    const float* x = (const float*)d_in[0];
    float* out = (float*)d_out;

    int B = out_size / 15;
    int T = in_sizes[0] / (7 * B);
    int nsteps = T - 1;

    // per-warp contiguous chunk, multiple of 256, 4 warps cover all steps
    int chunk = ((nsteps + 1023) / 1024) * 256;

    rmi_kernel<<<B, 128>>>(x, out, T, chunk);
}